// round 12
// baseline (speedup 1.0000x reference)
#include <cuda_runtime.h>
#include <cuda_fp16.h>
#include <cstdint>
#include <math.h>

// ---------------------------------------------------------------------------
// MinGRUCell on GB300 (sm_103a) — Round 12.
//   g = sigmoid(x Wg^T + bg), c = tanh(x Wh^T + bh)
//   h_t = g h_{t-1} + (1-g) c   (chunked affine scan along L)
// R11 profile: GEMM tensor=62.1%, occ=24.5% (2 CTA/SM, smem+regs bound),
// issue=34.5%, DRAM=12%. This round: 2-stage pipeline (64 KB smem) +
// __launch_bounds__(256,3) -> 3 CTAs/SM to cover barrier/ldsm gaps.
// ---------------------------------------------------------------------------

constexpr int B_  = 8;
constexpr int L_  = 4096;
constexpr int D_  = 1024;
constexpr int M_  = B_ * L_;     // 32768
constexpr int Nsz = D_;

constexpr int BM = 128, BN = 128;
constexpr int BKH   = 64;            // K per tile in halves (= 128 B rows)
constexpr int NKT   = D_ / BKH;      // 16
constexpr int STAGES = 2;
constexpr int TILE_B  = 128 * 128;   // one operand tile: 16 KB
constexpr int STAGE_B = 2 * TILE_B;  // A + B = 32 KB
constexpr int DYN_SMEM = STAGES * STAGE_B;   // 64 KB -> 3 CTAs/SM

constexpr int NC = 64;           // scan chunks
constexpr int CL = L_ / NC;      // 64

// Scratch
__device__ __half g_xh[(size_t)M_ * D_];        // x in fp16
__device__ __half g_wh[2 * (size_t)D_ * D_];    // [Wg | Wh] in fp16
__device__ float  g_gate[(size_t)M_ * D_];
__device__ float  g_cand[(size_t)M_ * D_];
__device__ float  g_Ac [B_ * NC * D_];
__device__ float  g_Bc [B_ * NC * D_];
__device__ float  g_hin[B_ * NC * D_];

// ---------------------------------------------------------------------------
// helpers
// ---------------------------------------------------------------------------
static __device__ __forceinline__ uint32_t smem_u32(const void* p) {
    uint32_t a;
    asm("{ .reg .u64 t; cvta.to.shared.u64 t, %1; cvt.u32.u64 %0, t; }" : "=r"(a) : "l"(p));
    return a;
}
static __device__ __forceinline__ void cp16(uint32_t sdst, const void* gsrc) {
    asm volatile("cp.async.cg.shared.global [%0], [%1], 16;"
                 :: "r"(sdst), "l"(__cvta_generic_to_global(gsrc)) : "memory");
}
#define CP_COMMIT() asm volatile("cp.async.commit_group;" ::: "memory")
template <int N>
static __device__ __forceinline__ void cp_wait() {
    asm volatile("cp.async.wait_group %0;" :: "n"(N) : "memory");
}
static __device__ __forceinline__ void ldsm4(uint32_t* r, uint32_t addr) {
    asm volatile("ldmatrix.sync.aligned.m8n8.x4.shared.b16 {%0,%1,%2,%3}, [%4];"
                 : "=r"(r[0]), "=r"(r[1]), "=r"(r[2]), "=r"(r[3]) : "r"(addr));
}
static __device__ __forceinline__ void mma16(float* c, const uint32_t* a, const uint32_t* b) {
    asm volatile(
        "mma.sync.aligned.m16n8k16.row.col.f32.f16.f16.f32 "
        "{%0,%1,%2,%3}, {%4,%5,%6,%7}, {%8,%9}, {%0,%1,%2,%3};\n"
        : "+f"(c[0]), "+f"(c[1]), "+f"(c[2]), "+f"(c[3])
        : "r"(a[0]), "r"(a[1]), "r"(a[2]), "r"(a[3]),
          "r"(b[0]), "r"(b[1]));
}

// ---------------------------------------------------------------------------
// P0: fp32 -> fp16 conversion (8 floats / thread, 16B stores)
// ---------------------------------------------------------------------------
__global__ void __launch_bounds__(256) to_half(const float* __restrict__ src,
                                               __half* __restrict__ dst, int n8)
{
    const int i = blockIdx.x * blockDim.x + threadIdx.x;
    if (i >= n8) return;
    const float4* s = (const float4*)src + 2 * (size_t)i;
    float4 a = s[0], b = s[1];
    __half2 h0 = __floats2half2_rn(a.x, a.y);
    __half2 h1 = __floats2half2_rn(a.z, a.w);
    __half2 h2 = __floats2half2_rn(b.x, b.y);
    __half2 h3 = __floats2half2_rn(b.z, b.w);
    uint4 o = make_uint4(*(uint32_t*)&h0, *(uint32_t*)&h1,
                         *(uint32_t*)&h2, *(uint32_t*)&h3);
    ((uint4*)dst)[i] = o;
}

// ---------------------------------------------------------------------------
// K1: fp16 GEMM, 2-stage cp.async pipeline + ldmatrix, 3 CTAs/SM target.
// C[m][n] = sum_k xh[m][k] * W[n][k]  (NT). grid.z: 0 = gate, 1 = cand.
// Block 256 (8 warps, 2x4); warp tile 64x32 -> 4x4 m16n8 tiles.
// SMEM tile: 128 rows x 64 halves, 16B-chunk XOR swizzle chunk^=(row&7).
// ---------------------------------------------------------------------------
__global__ void __launch_bounds__(256, 3) gemm_act_fp16(
    const float* __restrict__ bg, const float* __restrict__ bh)
{
    extern __shared__ char dyn[];
    const uint32_t dbase = smem_u32(dyn);

    const int zi = blockIdx.z;
    const __half* __restrict__ Wm = g_wh + (size_t)zi * D_ * D_;
    const float* __restrict__ bias = zi ? bh : bg;
    float* __restrict__ outp = zi ? g_cand : g_gate;

    const int tid  = threadIdx.x;
    const int m0   = blockIdx.y * BM;
    const int n0   = blockIdx.x * BN;
    const int warp = tid >> 5, lane = tid & 31;
    const int g    = lane >> 2;        // 0..7
    const int tg   = lane & 3;         // 0..3
    const int wm   = (warp >> 2) * 64; // 0 / 64
    const int wn   = (warp & 3) * 32;  // 0..96

    const __half* __restrict__ xa = g_xh + (size_t)m0 * D_;
    const __half* __restrict__ wb = Wm   + (size_t)n0 * D_;

    // Fragment ldmatrix lane geometry (x4):
    //   A(mt): row = wm + mt*16 + ((lane>>3)&1)*8 + (lane&7); chunk = ks*2 + (lane>>4)
    //   B(p):  row = wn + p*16  + (lane>>4)*8    + (lane&7); chunk = ks*2 + ((lane>>3)&1)
    const int lrow  = lane & 7;
    const int arow  = ((lane >> 3) & 1) * 8 + lrow;
    const int akadd = lane >> 4;
    const int brow  = (lane >> 4) * 8 + lrow;
    const int bkadd = (lane >> 3) & 1;

    float acc[4][4][4];
#pragma unroll
    for (int i = 0; i < 4; i++)
#pragma unroll
        for (int j = 0; j < 4; j++)
#pragma unroll
            for (int r = 0; r < 4; r++) acc[i][j][r] = 0.f;

    auto load_stage = [&](int stage, int kt) {
        const uint32_t sb = dbase + stage * STAGE_B;
#pragma unroll
        for (int i = 0; i < 4; i++) {
            const int f = tid + i * 256;
            const int row = f >> 3, chunk = f & 7;
            const uint32_t soff = (uint32_t)(row * 128 + ((chunk ^ (row & 7)) << 4));
            const size_t goff = (size_t)row * D_ + kt * BKH + chunk * 8;
            cp16(sb + soff, xa + goff);
            cp16(sb + TILE_B + soff, wb + goff);
        }
    };

    auto compute = [&](int stage) {
        const uint32_t sA = dbase + stage * STAGE_B;
        const uint32_t sB = sA + TILE_B;
#pragma unroll
        for (int ks = 0; ks < 4; ks++) {
            uint32_t af[4][4], bf[4][2];
#pragma unroll
            for (int mt = 0; mt < 4; mt++) {
                const int row = wm + mt * 16 + arow;
                const int ch  = (ks * 2 + akadd) ^ (row & 7);
                ldsm4(af[mt], sA + row * 128 + (ch << 4));
            }
#pragma unroll
            for (int p = 0; p < 2; p++) {
                const int row = wn + p * 16 + brow;
                const int ch  = (ks * 2 + bkadd) ^ (row & 7);
                uint32_t r4[4];
                ldsm4(r4, sB + row * 128 + (ch << 4));
                bf[2 * p][0]     = r4[0];
                bf[2 * p][1]     = r4[1];
                bf[2 * p + 1][0] = r4[2];
                bf[2 * p + 1][1] = r4[3];
            }
#pragma unroll
            for (int mt = 0; mt < 4; mt++)
#pragma unroll
                for (int nt = 0; nt < 4; nt++)
                    mma16(acc[mt][nt], af[mt], bf[nt]);
        }
    };

    // 2-stage pipeline: one cp.async group in flight during each compute.
    load_stage(0, 0); CP_COMMIT();

    for (int kt = 0; kt < NKT; kt++) {
        cp_wait<0>();                 // stage kt%2 copies complete
        __syncthreads();              // all warps done with compute(kt-1)
        if (kt + 1 < NKT) {
            load_stage((kt + 1) & 1, kt + 1);
            CP_COMMIT();
        }
        compute(kt & 1);
    }

    // Epilogue: bias + activation + fp32 store
    float bcol[8];
#pragma unroll
    for (int nt = 0; nt < 4; nt++) {
        const int col = n0 + wn + nt * 8 + tg * 2;
        bcol[nt * 2]     = bias[col];
        bcol[nt * 2 + 1] = bias[col + 1];
    }
#pragma unroll
    for (int mt = 0; mt < 4; mt++) {
#pragma unroll
        for (int nt = 0; nt < 4; nt++) {
            const int row = m0 + wm + mt * 16 + g;
            const int col = n0 + wn + nt * 8 + tg * 2;
#pragma unroll
            for (int h = 0; h < 2; h++) {
                const int r = row + h * 8;
                float z0 = acc[mt][nt][h * 2 + 0] + bcol[nt * 2];
                float z1 = acc[mt][nt][h * 2 + 1] + bcol[nt * 2 + 1];
                float v0, v1;
                if (zi == 0) {
                    v0 = 1.f / (1.f + expf(-z0));
                    v1 = 1.f / (1.f + expf(-z1));
                } else {
                    v0 = tanhf(z0);
                    v1 = tanhf(z1);
                }
                *(float2*)(outp + (size_t)r * Nsz + col) = make_float2(v0, v1);
            }
        }
    }
}

// ---------------------------------------------------------------------------
// Scan kernels (phase3: 80.9% DRAM, 6.4 TB/s — near roofline; unchanged).
// ---------------------------------------------------------------------------
__global__ void __launch_bounds__(256) scan_phase1()
{
    const int b = blockIdx.y, ch = blockIdx.x;
    const int d4 = threadIdx.x;
    const size_t base = ((size_t)(b * L_ + ch * CL) * D_) / 4 + d4;
    const float4* __restrict__ gp = (const float4*)g_gate + base;
    const float4* __restrict__ cp = (const float4*)g_cand + base;

    float4 A  = make_float4(1.f, 1.f, 1.f, 1.f);
    float4 Bv = make_float4(0.f, 0.f, 0.f, 0.f);
#pragma unroll 4
    for (int l = 0; l < CL; l++) {
        float4 gv = gp[(size_t)l * (D_ / 4)];
        float4 cv = cp[(size_t)l * (D_ / 4)];
        Bv.x = gv.x * Bv.x + (1.f - gv.x) * cv.x;  A.x *= gv.x;
        Bv.y = gv.y * Bv.y + (1.f - gv.y) * cv.y;  A.y *= gv.y;
        Bv.z = gv.z * Bv.z + (1.f - gv.z) * cv.z;  A.z *= gv.z;
        Bv.w = gv.w * Bv.w + (1.f - gv.w) * cv.w;  A.w *= gv.w;
    }
    const size_t o = ((size_t)(b * NC + ch) * D_) / 4 + d4;
    ((float4*)g_Ac)[o] = A;
    ((float4*)g_Bc)[o] = Bv;
}

__global__ void __launch_bounds__(256) scan_phase2(const float* __restrict__ hidden)
{
    const int idx = blockIdx.x * blockDim.x + threadIdx.x;   // 0..8191
    const int b = idx >> 10, d = idx & (D_ - 1);
    float h = hidden[idx];
#pragma unroll 8
    for (int c = 0; c < NC; c++) {
        const size_t o = (size_t)(b * NC + c) * D_ + d;
        g_hin[o] = h;
        h = g_Ac[o] * h + g_Bc[o];
    }
}

__global__ void __launch_bounds__(256) scan_phase3(float* __restrict__ out)
{
    const int b = blockIdx.y, ch = blockIdx.x;
    const int d4 = threadIdx.x;
    const size_t base = ((size_t)(b * L_ + ch * CL) * D_) / 4 + d4;
    const float4* __restrict__ gp = (const float4*)g_gate + base;
    const float4* __restrict__ cp = (const float4*)g_cand + base;
    float4* __restrict__ op = (float4*)out + base;

    float4 h = ((const float4*)g_hin)[((size_t)(b * NC + ch) * D_) / 4 + d4];
#pragma unroll 4
    for (int l = 0; l < CL; l++) {
        float4 gv = gp[(size_t)l * (D_ / 4)];
        float4 cv = cp[(size_t)l * (D_ / 4)];
        h.x = gv.x * h.x + (1.f - gv.x) * cv.x;
        h.y = gv.y * h.y + (1.f - gv.y) * cv.y;
        h.z = gv.z * h.z + (1.f - gv.z) * cv.z;
        h.w = gv.w * h.w + (1.f - gv.w) * cv.w;
        op[(size_t)l * (D_ / 4)] = h;
    }
}

// ---------------------------------------------------------------------------
extern "C" void kernel_launch(void* const* d_in, const int* in_sizes, int n_in,
                              void* d_out, int out_size)
{
    const float* x      = (const float*)d_in[0];
    const float* hidden = (const float*)d_in[1];
    const float* Wg     = (const float*)d_in[2];
    const float* bg     = (const float*)d_in[3];
    const float* Wh     = (const float*)d_in[4];
    const float* bh     = (const float*)d_in[5];
    float* out = (float*)d_out;

    // Unconditional + idempotent (no statics allowed in kernel_launch).
    cudaFuncSetAttribute(gemm_act_fp16,
                         cudaFuncAttributeMaxDynamicSharedMemorySize, DYN_SMEM);

    __half* xh = nullptr, *wh = nullptr;
    cudaGetSymbolAddress((void**)&xh, g_xh);
    cudaGetSymbolAddress((void**)&wh, g_wh);

    // P0: fp32 -> fp16
    to_half<<<(M_ * D_ / 8 + 255) / 256, 256>>>(x, xh, M_ * D_ / 8);
    to_half<<<(D_ * D_ / 8 + 255) / 256, 256>>>(Wg, wh, D_ * D_ / 8);
    to_half<<<(D_ * D_ / 8 + 255) / 256, 256>>>(Wh, wh + (size_t)D_ * D_, D_ * D_ / 8);

    // K1: dual GEMM (z = gate/cand)
    gemm_act_fp16<<<dim3(Nsz / BN, M_ / BM, 2), 256, DYN_SMEM>>>(bg, bh);

    // K2..K4: scan
    scan_phase1<<<dim3(NC, B_), 256>>>();
    scan_phase2<<<(B_ * D_) / 256, 256>>>(hidden);
    scan_phase3<<<dim3(NC, B_), 256>>>(out);
}

// round 14
// speedup vs baseline: 1.4676x; 1.4676x over previous
#include <cuda_runtime.h>
#include <cuda_fp16.h>
#include <cstdint>
#include <math.h>

// ---------------------------------------------------------------------------
// MinGRUCell on GB300 (sm_103a) — Round 13.
//   g = sigmoid(x Wg^T + bg), c = tanh(x Wh^T + bh)
//   h_t = g h_{t-1} + (1-g) c   (chunked affine scan along L)
// Base = R11 (3-stage cp.async, 96 KB, ldmatrix, 367us GEMM @ tensor 62%).
// R12 taught: no reg squeeze (spills), no 2-stage (serializes).
// This round: double-buffered ldmatrix fragments — prefetch ks+1 frags
// before issuing ks MMAs, hiding LDS latency inside the warp.
// ---------------------------------------------------------------------------

constexpr int B_  = 8;
constexpr int L_  = 4096;
constexpr int D_  = 1024;
constexpr int M_  = B_ * L_;     // 32768
constexpr int Nsz = D_;

constexpr int BM = 128, BN = 128;
constexpr int BKH   = 64;            // K per tile in halves (= 128 B rows)
constexpr int NKT   = D_ / BKH;      // 16
constexpr int STAGES = 3;
constexpr int TILE_B  = 128 * 128;   // one operand tile: 16 KB
constexpr int STAGE_B = 2 * TILE_B;  // A + B
constexpr int DYN_SMEM = STAGES * STAGE_B;   // 96 KB

constexpr int NC = 64;           // scan chunks
constexpr int CL = L_ / NC;      // 64

// Scratch
__device__ __half g_xh[(size_t)M_ * D_];        // x in fp16
__device__ __half g_wh[2 * (size_t)D_ * D_];    // [Wg | Wh] in fp16
__device__ float  g_gate[(size_t)M_ * D_];
__device__ float  g_cand[(size_t)M_ * D_];
__device__ float  g_Ac [B_ * NC * D_];
__device__ float  g_Bc [B_ * NC * D_];
__device__ float  g_hin[B_ * NC * D_];

// ---------------------------------------------------------------------------
// helpers
// ---------------------------------------------------------------------------
static __device__ __forceinline__ uint32_t smem_u32(const void* p) {
    uint32_t a;
    asm("{ .reg .u64 t; cvta.to.shared.u64 t, %1; cvt.u32.u64 %0, t; }" : "=r"(a) : "l"(p));
    return a;
}
static __device__ __forceinline__ void cp16(uint32_t sdst, const void* gsrc) {
    asm volatile("cp.async.cg.shared.global [%0], [%1], 16;"
                 :: "r"(sdst), "l"(__cvta_generic_to_global(gsrc)) : "memory");
}
#define CP_COMMIT() asm volatile("cp.async.commit_group;" ::: "memory")
template <int N>
static __device__ __forceinline__ void cp_wait() {
    asm volatile("cp.async.wait_group %0;" :: "n"(N) : "memory");
}
static __device__ __forceinline__ void ldsm4(uint32_t* r, uint32_t addr) {
    asm volatile("ldmatrix.sync.aligned.m8n8.x4.shared.b16 {%0,%1,%2,%3}, [%4];"
                 : "=r"(r[0]), "=r"(r[1]), "=r"(r[2]), "=r"(r[3]) : "r"(addr));
}
static __device__ __forceinline__ void mma16(float* c, const uint32_t* a, const uint32_t* b) {
    asm volatile(
        "mma.sync.aligned.m16n8k16.row.col.f32.f16.f16.f32 "
        "{%0,%1,%2,%3}, {%4,%5,%6,%7}, {%8,%9}, {%0,%1,%2,%3};\n"
        : "+f"(c[0]), "+f"(c[1]), "+f"(c[2]), "+f"(c[3])
        : "r"(a[0]), "r"(a[1]), "r"(a[2]), "r"(a[3]),
          "r"(b[0]), "r"(b[1]));
}

// ---------------------------------------------------------------------------
// P0: fp32 -> fp16 conversion (8 floats / thread, 16B stores)
// ---------------------------------------------------------------------------
__global__ void __launch_bounds__(256) to_half(const float* __restrict__ src,
                                               __half* __restrict__ dst, int n8)
{
    const int i = blockIdx.x * blockDim.x + threadIdx.x;
    if (i >= n8) return;
    const float4* s = (const float4*)src + 2 * (size_t)i;
    float4 a = s[0], b = s[1];
    __half2 h0 = __floats2half2_rn(a.x, a.y);
    __half2 h1 = __floats2half2_rn(a.z, a.w);
    __half2 h2 = __floats2half2_rn(b.x, b.y);
    __half2 h3 = __floats2half2_rn(b.z, b.w);
    uint4 o = make_uint4(*(uint32_t*)&h0, *(uint32_t*)&h1,
                         *(uint32_t*)&h2, *(uint32_t*)&h3);
    ((uint4*)dst)[i] = o;
}

// ---------------------------------------------------------------------------
// K1: fp16 GEMM, 3-stage cp.async + double-buffered ldmatrix fragments.
// C[m][n] = sum_k xh[m][k] * W[n][k]  (NT). grid.z: 0 = gate, 1 = cand.
// Block 256 (8 warps, 2x4); warp tile 64x32 -> 4x4 m16n8 tiles.
// SMEM tile: 128 rows x 64 halves, 16B-chunk XOR swizzle chunk^=(row&7).
// ---------------------------------------------------------------------------
__global__ void __launch_bounds__(256) gemm_act_fp16(
    const float* __restrict__ bg, const float* __restrict__ bh)
{
    extern __shared__ char dyn[];
    const uint32_t dbase = smem_u32(dyn);

    const int zi = blockIdx.z;
    const __half* __restrict__ Wm = g_wh + (size_t)zi * D_ * D_;
    const float* __restrict__ bias = zi ? bh : bg;
    float* __restrict__ outp = zi ? g_cand : g_gate;

    const int tid  = threadIdx.x;
    const int m0   = blockIdx.y * BM;
    const int n0   = blockIdx.x * BN;
    const int warp = tid >> 5, lane = tid & 31;
    const int g    = lane >> 2;        // 0..7
    const int tg   = lane & 3;         // 0..3
    const int wm   = (warp >> 2) * 64; // 0 / 64
    const int wn   = (warp & 3) * 32;  // 0..96

    const __half* __restrict__ xa = g_xh + (size_t)m0 * D_;
    const __half* __restrict__ wb = Wm   + (size_t)n0 * D_;

    // Fragment ldmatrix lane geometry (x4):
    //   A(mt): row = wm + mt*16 + ((lane>>3)&1)*8 + (lane&7); chunk = ks*2 + (lane>>4)
    //   B(p):  row = wn + p*16  + (lane>>4)*8    + (lane&7); chunk = ks*2 + ((lane>>3)&1)
    const int lrow  = lane & 7;
    const int arow  = ((lane >> 3) & 1) * 8 + lrow;
    const int akadd = lane >> 4;
    const int brow  = (lane >> 4) * 8 + lrow;
    const int bkadd = (lane >> 3) & 1;

    float acc[4][4][4];
#pragma unroll
    for (int i = 0; i < 4; i++)
#pragma unroll
        for (int j = 0; j < 4; j++)
#pragma unroll
            for (int r = 0; r < 4; r++) acc[i][j][r] = 0.f;

    auto load_stage = [&](int stage, int kt) {
        const uint32_t sb = dbase + stage * STAGE_B;
#pragma unroll
        for (int i = 0; i < 4; i++) {
            const int f = tid + i * 256;
            const int row = f >> 3, chunk = f & 7;
            const uint32_t soff = (uint32_t)(row * 128 + ((chunk ^ (row & 7)) << 4));
            const size_t goff = (size_t)row * D_ + kt * BKH + chunk * 8;
            cp16(sb + soff, xa + goff);
            cp16(sb + TILE_B + soff, wb + goff);
        }
    };

    // load fragments for one ks step of a stage into the given buffers
    auto ld_frags = [&](uint32_t sA, uint32_t sB, int ks,
                        uint32_t af[4][4], uint32_t bf[4][2]) {
#pragma unroll
        for (int mt = 0; mt < 4; mt++) {
            const int row = wm + mt * 16 + arow;
            const int ch  = (ks * 2 + akadd) ^ (row & 7);
            ldsm4(af[mt], sA + row * 128 + (ch << 4));
        }
#pragma unroll
        for (int p = 0; p < 2; p++) {
            const int row = wn + p * 16 + brow;
            const int ch  = (ks * 2 + bkadd) ^ (row & 7);
            uint32_t r4[4];
            ldsm4(r4, sB + row * 128 + (ch << 4));
            bf[2 * p][0]     = r4[0];
            bf[2 * p][1]     = r4[1];
            bf[2 * p + 1][0] = r4[2];
            bf[2 * p + 1][1] = r4[3];
        }
    };

    auto mma_all = [&](uint32_t af[4][4], uint32_t bf[4][2]) {
#pragma unroll
        for (int mt = 0; mt < 4; mt++)
#pragma unroll
            for (int nt = 0; nt < 4; nt++)
                mma16(acc[mt][nt], af[mt], bf[nt]);
    };

    // prologue: prefetch stages 0, 1
    load_stage(0, 0); CP_COMMIT();
    load_stage(1, 1); CP_COMMIT();

    uint32_t afb[2][4][4], bfb[2][4][2];

    for (int kt = 0; kt < NKT; kt++) {
        cp_wait<STAGES - 2>();        // stage kt%STAGES copies complete
        __syncthreads();              // all warps done reading the refill target
        const int pf = kt + STAGES - 1;
        if (pf < NKT) load_stage(pf % STAGES, pf);
        CP_COMMIT();                  // keep group accounting aligned

        const uint32_t sA = dbase + (kt % STAGES) * STAGE_B;
        const uint32_t sB = sA + TILE_B;

        // double-buffered fragment pipeline over ks = 0..3
        ld_frags(sA, sB, 0, afb[0], bfb[0]);
#pragma unroll
        for (int ks = 0; ks < 4; ks++) {
            const int cur = ks & 1;
            if (ks < 3)
                ld_frags(sA, sB, ks + 1, afb[cur ^ 1], bfb[cur ^ 1]);
            mma_all(afb[cur], bfb[cur]);
        }
    }

    // Epilogue: bias + activation + fp32 store
    float bcol[8];
#pragma unroll
    for (int nt = 0; nt < 4; nt++) {
        const int col = n0 + wn + nt * 8 + tg * 2;
        bcol[nt * 2]     = bias[col];
        bcol[nt * 2 + 1] = bias[col + 1];
    }
#pragma unroll
    for (int mt = 0; mt < 4; mt++) {
#pragma unroll
        for (int nt = 0; nt < 4; nt++) {
            const int row = m0 + wm + mt * 16 + g;
            const int col = n0 + wn + nt * 8 + tg * 2;
#pragma unroll
            for (int h = 0; h < 2; h++) {
                const int r = row + h * 8;
                float z0 = acc[mt][nt][h * 2 + 0] + bcol[nt * 2];
                float z1 = acc[mt][nt][h * 2 + 1] + bcol[nt * 2 + 1];
                float v0, v1;
                if (zi == 0) {
                    v0 = 1.f / (1.f + expf(-z0));
                    v1 = 1.f / (1.f + expf(-z1));
                } else {
                    v0 = tanhf(z0);
                    v1 = tanhf(z1);
                }
                *(float2*)(outp + (size_t)r * Nsz + col) = make_float2(v0, v1);
            }
        }
    }
}

// ---------------------------------------------------------------------------
// Scan kernels (phase3: 80.9% DRAM, 6.4 TB/s — near roofline; unchanged).
// ---------------------------------------------------------------------------
__global__ void __launch_bounds__(256) scan_phase1()
{
    const int b = blockIdx.y, ch = blockIdx.x;
    const int d4 = threadIdx.x;
    const size_t base = ((size_t)(b * L_ + ch * CL) * D_) / 4 + d4;
    const float4* __restrict__ gp = (const float4*)g_gate + base;
    const float4* __restrict__ cp = (const float4*)g_cand + base;

    float4 A  = make_float4(1.f, 1.f, 1.f, 1.f);
    float4 Bv = make_float4(0.f, 0.f, 0.f, 0.f);
#pragma unroll 4
    for (int l = 0; l < CL; l++) {
        float4 gv = gp[(size_t)l * (D_ / 4)];
        float4 cv = cp[(size_t)l * (D_ / 4)];
        Bv.x = gv.x * Bv.x + (1.f - gv.x) * cv.x;  A.x *= gv.x;
        Bv.y = gv.y * Bv.y + (1.f - gv.y) * cv.y;  A.y *= gv.y;
        Bv.z = gv.z * Bv.z + (1.f - gv.z) * cv.z;  A.z *= gv.z;
        Bv.w = gv.w * Bv.w + (1.f - gv.w) * cv.w;  A.w *= gv.w;
    }
    const size_t o = ((size_t)(b * NC + ch) * D_) / 4 + d4;
    ((float4*)g_Ac)[o] = A;
    ((float4*)g_Bc)[o] = Bv;
}

__global__ void __launch_bounds__(256) scan_phase2(const float* __restrict__ hidden)
{
    const int idx = blockIdx.x * blockDim.x + threadIdx.x;   // 0..8191
    const int b = idx >> 10, d = idx & (D_ - 1);
    float h = hidden[idx];
#pragma unroll 8
    for (int c = 0; c < NC; c++) {
        const size_t o = (size_t)(b * NC + c) * D_ + d;
        g_hin[o] = h;
        h = g_Ac[o] * h + g_Bc[o];
    }
}

__global__ void __launch_bounds__(256) scan_phase3(float* __restrict__ out)
{
    const int b = blockIdx.y, ch = blockIdx.x;
    const int d4 = threadIdx.x;
    const size_t base = ((size_t)(b * L_ + ch * CL) * D_) / 4 + d4;
    const float4* __restrict__ gp = (const float4*)g_gate + base;
    const float4* __restrict__ cp = (const float4*)g_cand + base;
    float4* __restrict__ op = (float4*)out + base;

    float4 h = ((const float4*)g_hin)[((size_t)(b * NC + ch) * D_) / 4 + d4];
#pragma unroll 4
    for (int l = 0; l < CL; l++) {
        float4 gv = gp[(size_t)l * (D_ / 4)];
        float4 cv = cp[(size_t)l * (D_ / 4)];
        h.x = gv.x * h.x + (1.f - gv.x) * cv.x;
        h.y = gv.y * h.y + (1.f - gv.y) * cv.y;
        h.z = gv.z * h.z + (1.f - gv.z) * cv.z;
        h.w = gv.w * h.w + (1.f - gv.w) * cv.w;
        op[(size_t)l * (D_ / 4)] = h;
    }
}

// ---------------------------------------------------------------------------
extern "C" void kernel_launch(void* const* d_in, const int* in_sizes, int n_in,
                              void* d_out, int out_size)
{
    const float* x      = (const float*)d_in[0];
    const float* hidden = (const float*)d_in[1];
    const float* Wg     = (const float*)d_in[2];
    const float* bg     = (const float*)d_in[3];
    const float* Wh     = (const float*)d_in[4];
    const float* bh     = (const float*)d_in[5];
    float* out = (float*)d_out;

    // Unconditional + idempotent (no statics allowed in kernel_launch).
    cudaFuncSetAttribute(gemm_act_fp16,
                         cudaFuncAttributeMaxDynamicSharedMemorySize, DYN_SMEM);

    __half* xh = nullptr, *wh = nullptr;
    cudaGetSymbolAddress((void**)&xh, g_xh);
    cudaGetSymbolAddress((void**)&wh, g_wh);

    // P0: fp32 -> fp16
    to_half<<<(M_ * D_ / 8 + 255) / 256, 256>>>(x, xh, M_ * D_ / 8);
    to_half<<<(D_ * D_ / 8 + 255) / 256, 256>>>(Wg, wh, D_ * D_ / 8);
    to_half<<<(D_ * D_ / 8 + 255) / 256, 256>>>(Wh, wh + (size_t)D_ * D_, D_ * D_ / 8);

    // K1: dual GEMM (z = gate/cand)
    gemm_act_fp16<<<dim3(Nsz / BN, M_ / BM, 2), 256, DYN_SMEM>>>(bg, bh);

    // K2..K4: scan
    scan_phase1<<<dim3(NC, B_), 256>>>();
    scan_phase2<<<(B_ * D_) / 256, 256>>>(hidden);
    scan_phase3<<<dim3(NC, B_), 256>>>(out);
}

// round 17
// speedup vs baseline: 1.5974x; 1.0884x over previous
#include <cuda_runtime.h>
#include <cuda_fp16.h>
#include <cstdint>
#include <math.h>

// ---------------------------------------------------------------------------
// MinGRUCell on GB300 (sm_103a) — Round 15.
//   g = sigmoid(x Wg^T + bg), c = tanh(x Wh^T + bh)
//   h_t = g h_{t-1} + (1-g) c   (chunked affine scan along L)
// R13 GEMM kept verbatim (352us, tensor 64.8%). This round: g/c stored as
// fp16 (halves scan-phase DRAM traffic, scan is 80% DRAM-bound at 6.4TB/s).
// Predicted rel_err ~6e-4 (fp16 quantization of g,c through the contraction
// scan), under the 1e-3 threshold.
// ---------------------------------------------------------------------------

constexpr int B_  = 8;
constexpr int L_  = 4096;
constexpr int D_  = 1024;
constexpr int M_  = B_ * L_;     // 32768
constexpr int Nsz = D_;

constexpr int BM = 128, BN = 128;
constexpr int BKH   = 64;            // K per tile in halves (= 128 B rows)
constexpr int NKT   = D_ / BKH;      // 16
constexpr int STAGES = 3;
constexpr int TILE_B  = 128 * 128;   // one operand tile: 16 KB
constexpr int STAGE_B = 2 * TILE_B;  // A + B
constexpr int DYN_SMEM = STAGES * STAGE_B;   // 96 KB

constexpr int NC = 64;           // scan chunks
constexpr int CL = L_ / NC;      // 64

// Scratch
__device__ __half g_xh[(size_t)M_ * D_];        // x in fp16
__device__ __half g_wh[2 * (size_t)D_ * D_];    // [Wg | Wh] in fp16
__device__ __half g_gate[(size_t)M_ * D_];      // sigmoid(...) in fp16
__device__ __half g_cand[(size_t)M_ * D_];      // tanh(...) in fp16
__device__ float  g_Ac [B_ * NC * D_];
__device__ float  g_Bc [B_ * NC * D_];
__device__ float  g_hin[B_ * NC * D_];

// ---------------------------------------------------------------------------
// helpers
// ---------------------------------------------------------------------------
static __device__ __forceinline__ uint32_t smem_u32(const void* p) {
    uint32_t a;
    asm("{ .reg .u64 t; cvta.to.shared.u64 t, %1; cvt.u32.u64 %0, t; }" : "=r"(a) : "l"(p));
    return a;
}
static __device__ __forceinline__ void cp16(uint32_t sdst, const void* gsrc) {
    asm volatile("cp.async.cg.shared.global [%0], [%1], 16;"
                 :: "r"(sdst), "l"(__cvta_generic_to_global(gsrc)) : "memory");
}
#define CP_COMMIT() asm volatile("cp.async.commit_group;" ::: "memory")
template <int N>
static __device__ __forceinline__ void cp_wait() {
    asm volatile("cp.async.wait_group %0;" :: "n"(N) : "memory");
}
static __device__ __forceinline__ void ldsm4(uint32_t* r, uint32_t addr) {
    asm volatile("ldmatrix.sync.aligned.m8n8.x4.shared.b16 {%0,%1,%2,%3}, [%4];"
                 : "=r"(r[0]), "=r"(r[1]), "=r"(r[2]), "=r"(r[3]) : "r"(addr));
}
static __device__ __forceinline__ void mma16(float* c, const uint32_t* a, const uint32_t* b) {
    asm volatile(
        "mma.sync.aligned.m16n8k16.row.col.f32.f16.f16.f32 "
        "{%0,%1,%2,%3}, {%4,%5,%6,%7}, {%8,%9}, {%0,%1,%2,%3};\n"
        : "+f"(c[0]), "+f"(c[1]), "+f"(c[2]), "+f"(c[3])
        : "r"(a[0]), "r"(a[1]), "r"(a[2]), "r"(a[3]),
          "r"(b[0]), "r"(b[1]));
}

// ---------------------------------------------------------------------------
// P0: fp32 -> fp16 conversion (8 floats / thread, 16B stores)
// ---------------------------------------------------------------------------
__global__ void __launch_bounds__(256) to_half(const float* __restrict__ src,
                                               __half* __restrict__ dst, int n8)
{
    const int i = blockIdx.x * blockDim.x + threadIdx.x;
    if (i >= n8) return;
    const float4* s = (const float4*)src + 2 * (size_t)i;
    float4 a = s[0], b = s[1];
    __half2 h0 = __floats2half2_rn(a.x, a.y);
    __half2 h1 = __floats2half2_rn(a.z, a.w);
    __half2 h2 = __floats2half2_rn(b.x, b.y);
    __half2 h3 = __floats2half2_rn(b.z, b.w);
    uint4 o = make_uint4(*(uint32_t*)&h0, *(uint32_t*)&h1,
                         *(uint32_t*)&h2, *(uint32_t*)&h3);
    ((uint4*)dst)[i] = o;
}

// ---------------------------------------------------------------------------
// K1: fp16 GEMM, 3-stage cp.async + double-buffered ldmatrix fragments.
// Identical mainloop to R13 (352us, tensor 64.8%). Epilogue now stores
// half2-packed activations.
// ---------------------------------------------------------------------------
__global__ void __launch_bounds__(256) gemm_act_fp16(
    const float* __restrict__ bg, const float* __restrict__ bh)
{
    extern __shared__ char dyn[];
    const uint32_t dbase = smem_u32(dyn);

    const int zi = blockIdx.z;
    const __half* __restrict__ Wm = g_wh + (size_t)zi * D_ * D_;
    const float* __restrict__ bias = zi ? bh : bg;
    __half* __restrict__ outp = zi ? g_cand : g_gate;

    const int tid  = threadIdx.x;
    const int m0   = blockIdx.y * BM;
    const int n0   = blockIdx.x * BN;
    const int warp = tid >> 5, lane = tid & 31;
    const int g    = lane >> 2;        // 0..7
    const int tg   = lane & 3;         // 0..3
    const int wm   = (warp >> 2) * 64; // 0 / 64
    const int wn   = (warp & 3) * 32;  // 0..96

    const __half* __restrict__ xa = g_xh + (size_t)m0 * D_;
    const __half* __restrict__ wb = Wm   + (size_t)n0 * D_;

    const int lrow  = lane & 7;
    const int arow  = ((lane >> 3) & 1) * 8 + lrow;
    const int akadd = lane >> 4;
    const int brow  = (lane >> 4) * 8 + lrow;
    const int bkadd = (lane >> 3) & 1;

    float acc[4][4][4];
#pragma unroll
    for (int i = 0; i < 4; i++)
#pragma unroll
        for (int j = 0; j < 4; j++)
#pragma unroll
            for (int r = 0; r < 4; r++) acc[i][j][r] = 0.f;

    auto load_stage = [&](int stage, int kt) {
        const uint32_t sb = dbase + stage * STAGE_B;
#pragma unroll
        for (int i = 0; i < 4; i++) {
            const int f = tid + i * 256;
            const int row = f >> 3, chunk = f & 7;
            const uint32_t soff = (uint32_t)(row * 128 + ((chunk ^ (row & 7)) << 4));
            const size_t goff = (size_t)row * D_ + kt * BKH + chunk * 8;
            cp16(sb + soff, xa + goff);
            cp16(sb + TILE_B + soff, wb + goff);
        }
    };

    auto ld_frags = [&](uint32_t sA, uint32_t sB, int ks,
                        uint32_t af[4][4], uint32_t bf[4][2]) {
#pragma unroll
        for (int mt = 0; mt < 4; mt++) {
            const int row = wm + mt * 16 + arow;
            const int ch  = (ks * 2 + akadd) ^ (row & 7);
            ldsm4(af[mt], sA + row * 128 + (ch << 4));
        }
#pragma unroll
        for (int p = 0; p < 2; p++) {
            const int row = wn + p * 16 + brow;
            const int ch  = (ks * 2 + bkadd) ^ (row & 7);
            uint32_t r4[4];
            ldsm4(r4, sB + row * 128 + (ch << 4));
            bf[2 * p][0]     = r4[0];
            bf[2 * p][1]     = r4[1];
            bf[2 * p + 1][0] = r4[2];
            bf[2 * p + 1][1] = r4[3];
        }
    };

    auto mma_all = [&](uint32_t af[4][4], uint32_t bf[4][2]) {
#pragma unroll
        for (int mt = 0; mt < 4; mt++)
#pragma unroll
            for (int nt = 0; nt < 4; nt++)
                mma16(acc[mt][nt], af[mt], bf[nt]);
    };

    load_stage(0, 0); CP_COMMIT();
    load_stage(1, 1); CP_COMMIT();

    uint32_t afb[2][4][4], bfb[2][4][2];

    for (int kt = 0; kt < NKT; kt++) {
        cp_wait<STAGES - 2>();
        __syncthreads();
        const int pf = kt + STAGES - 1;
        if (pf < NKT) load_stage(pf % STAGES, pf);
        CP_COMMIT();

        const uint32_t sA = dbase + (kt % STAGES) * STAGE_B;
        const uint32_t sB = sA + TILE_B;

        ld_frags(sA, sB, 0, afb[0], bfb[0]);
#pragma unroll
        for (int ks = 0; ks < 4; ks++) {
            const int cur = ks & 1;
            if (ks < 3)
                ld_frags(sA, sB, ks + 1, afb[cur ^ 1], bfb[cur ^ 1]);
            mma_all(afb[cur], bfb[cur]);
        }
    }

    // Epilogue: bias + activation + fp16 store (half2 per col pair)
    float bcol[8];
#pragma unroll
    for (int nt = 0; nt < 4; nt++) {
        const int col = n0 + wn + nt * 8 + tg * 2;
        bcol[nt * 2]     = bias[col];
        bcol[nt * 2 + 1] = bias[col + 1];
    }
#pragma unroll
    for (int mt = 0; mt < 4; mt++) {
#pragma unroll
        for (int nt = 0; nt < 4; nt++) {
            const int row = m0 + wm + mt * 16 + g;
            const int col = n0 + wn + nt * 8 + tg * 2;
#pragma unroll
            for (int h = 0; h < 2; h++) {
                const int r = row + h * 8;
                float z0 = acc[mt][nt][h * 2 + 0] + bcol[nt * 2];
                float z1 = acc[mt][nt][h * 2 + 1] + bcol[nt * 2 + 1];
                float v0, v1;
                if (zi == 0) {
                    v0 = 1.f / (1.f + expf(-z0));
                    v1 = 1.f / (1.f + expf(-z1));
                } else {
                    v0 = tanhf(z0);
                    v1 = tanhf(z1);
                }
                __half2 hv = __floats2half2_rn(v0, v1);
                *(uint32_t*)(outp + (size_t)r * Nsz + col) = *(uint32_t*)&hv;
            }
        }
    }
}

// ---------------------------------------------------------------------------
// Scan kernels — g/c now fp16 (half the read traffic; DRAM-bound at 6.4TB/s).
// Thread t owns channels d = 4t..4t+3: uint2 = 4 halves per step.
// ---------------------------------------------------------------------------
__global__ void __launch_bounds__(256) scan_phase1()
{
    const int b = blockIdx.y, ch = blockIdx.x;
    const int d4 = threadIdx.x;
    const size_t eb = (size_t)(b * L_ + ch * CL) * D_ + d4 * 4;
    const uint2* __restrict__ gp = (const uint2*)(g_gate + eb);
    const uint2* __restrict__ cp = (const uint2*)(g_cand + eb);

    float4 A  = make_float4(1.f, 1.f, 1.f, 1.f);
    float4 Bv = make_float4(0.f, 0.f, 0.f, 0.f);
#pragma unroll 4
    for (int l = 0; l < CL; l++) {
        uint2 gu = gp[(size_t)l * (D_ / 4)];
        uint2 cu = cp[(size_t)l * (D_ / 4)];
        float2 g01 = __half22float2(*(__half2*)&gu.x);
        float2 g23 = __half22float2(*(__half2*)&gu.y);
        float2 c01 = __half22float2(*(__half2*)&cu.x);
        float2 c23 = __half22float2(*(__half2*)&cu.y);
        Bv.x = g01.x * Bv.x + (1.f - g01.x) * c01.x;  A.x *= g01.x;
        Bv.y = g01.y * Bv.y + (1.f - g01.y) * c01.y;  A.y *= g01.y;
        Bv.z = g23.x * Bv.z + (1.f - g23.x) * c23.x;  A.z *= g23.x;
        Bv.w = g23.y * Bv.w + (1.f - g23.y) * c23.y;  A.w *= g23.y;
    }
    const size_t o = ((size_t)(b * NC + ch) * D_) / 4 + d4;
    ((float4*)g_Ac)[o] = A;
    ((float4*)g_Bc)[o] = Bv;
}

__global__ void __launch_bounds__(256) scan_phase2(const float* __restrict__ hidden)
{
    const int idx = blockIdx.x * blockDim.x + threadIdx.x;   // 0..8191
    const int b = idx >> 10, d = idx & (D_ - 1);
    float h = hidden[idx];
#pragma unroll 8
    for (int c = 0; c < NC; c++) {
        const size_t o = (size_t)(b * NC + c) * D_ + d;
        g_hin[o] = h;
        h = g_Ac[o] * h + g_Bc[o];
    }
}

__global__ void __launch_bounds__(256) scan_phase3(float* __restrict__ out)
{
    const int b = blockIdx.y, ch = blockIdx.x;
    const int d4 = threadIdx.x;
    const size_t eb = (size_t)(b * L_ + ch * CL) * D_ + d4 * 4;
    const uint2* __restrict__ gp = (const uint2*)(g_gate + eb);
    const uint2* __restrict__ cp = (const uint2*)(g_cand + eb);
    float4* __restrict__ op = (float4*)(out + eb);

    float4 h = ((const float4*)g_hin)[((size_t)(b * NC + ch) * D_) / 4 + d4];
#pragma unroll 4
    for (int l = 0; l < CL; l++) {
        uint2 gu = gp[(size_t)l * (D_ / 4)];
        uint2 cu = cp[(size_t)l * (D_ / 4)];
        float2 g01 = __half22float2(*(__half2*)&gu.x);
        float2 g23 = __half22float2(*(__half2*)&gu.y);
        float2 c01 = __half22float2(*(__half2*)&cu.x);
        float2 c23 = __half22float2(*(__half2*)&cu.y);
        h.x = g01.x * h.x + (1.f - g01.x) * c01.x;
        h.y = g01.y * h.y + (1.f - g01.y) * c01.y;
        h.z = g23.x * h.z + (1.f - g23.x) * c23.x;
        h.w = g23.y * h.w + (1.f - g23.y) * c23.y;
        op[(size_t)l * (D_ / 4)] = h;
    }
}

// ---------------------------------------------------------------------------
extern "C" void kernel_launch(void* const* d_in, const int* in_sizes, int n_in,
                              void* d_out, int out_size)
{
    const float* x      = (const float*)d_in[0];
    const float* hidden = (const float*)d_in[1];
    const float* Wg     = (const float*)d_in[2];
    const float* bg     = (const float*)d_in[3];
    const float* Wh     = (const float*)d_in[4];
    const float* bh     = (const float*)d_in[5];
    float* out = (float*)d_out;

    cudaFuncSetAttribute(gemm_act_fp16,
                         cudaFuncAttributeMaxDynamicSharedMemorySize, DYN_SMEM);

    __half* xh = nullptr, *wh = nullptr;
    cudaGetSymbolAddress((void**)&xh, g_xh);
    cudaGetSymbolAddress((void**)&wh, g_wh);

    // P0: fp32 -> fp16
    to_half<<<(M_ * D_ / 8 + 255) / 256, 256>>>(x, xh, M_ * D_ / 8);
    to_half<<<(D_ * D_ / 8 + 255) / 256, 256>>>(Wg, wh, D_ * D_ / 8);
    to_half<<<(D_ * D_ / 8 + 255) / 256, 256>>>(Wh, wh + (size_t)D_ * D_, D_ * D_ / 8);

    // K1: dual GEMM (z = gate/cand)
    gemm_act_fp16<<<dim3(Nsz / BN, M_ / BM, 2), 256, DYN_SMEM>>>(bg, bh);

    // K2..K4: scan
    scan_phase1<<<dim3(NC, B_), 256>>>();
    scan_phase2<<<(B_ * D_) / 256, 256>>>(hidden);
    scan_phase3<<<dim3(NC, B_), 256>>>(out);
}